// round 7
// baseline (speedup 1.0000x reference)
#include <cuda_runtime.h>
#include <cuda_bf16.h>
#include <cstdint>

// Problem constants (from reference):
//   R_MAX=32, S_MAX=2 -> C_R = 66, C_S = 6, DIM_PAIR = 128
//   W rows: [0,66) = W_si, [66,132) = W_ti, 132 = w_ent, [133,139) = W_sym
#define DIM   128
#define NCTA  304    // 2 CTAs/SM on 152-SM GB300

__device__ __forceinline__ void stg256_cs(float* p, float4 a, float4 b)
{
    // 256-bit streaming store (sm_100+). 32B-aligned by construction.
    asm volatile("st.global.cs.v8.f32 [%0], {%1,%2,%3,%4,%5,%6,%7,%8};"
                 :: "l"(p),
                    "f"(a.x), "f"(a.y), "f"(a.z), "f"(a.w),
                    "f"(b.x), "f"(b.y), "f"(b.z), "f"(b.w)
                 : "memory");
}

__global__ __launch_bounds__(1024, 2)
void rpe_kernel(const int* __restrict__ seq_index,
                const int* __restrict__ seq_color,
                const int* __restrict__ seq_sym,
                const int* __restrict__ seq_entity,
                const int* __restrict__ token_index,
                const float* __restrict__ W,
                float* __restrict__ out,
                int L)
{
    // Tables (folded):
    //   sT1[d]  = W_si[d] + W_ti[65]      (66 rows) — d_ti==65 fast path folded in
    //   sSym[d] = W_sym[d] + (d!=5)*w_ent (6 rows)  — bij_entity <=> d_sym!=5
    //   skey[j] = color | entity<<2 | sym<<4 | seq_index<<6 | token_index<<16
    __shared__ float    sT1[66 * DIM];
    __shared__ float    sSym[6 * DIM];
    __shared__ unsigned skey[1024];

    const int tid = threadIdx.x;

    for (int idx = tid; idx < 66 * DIM; idx += blockDim.x) {
        int k = idx & (DIM - 1);
        sT1[idx] = W[idx] + W[131 * DIM + k];
    }
    for (int idx = tid; idx < 6 * DIM; idx += blockDim.x) {
        int d = idx >> 7, k = idx & (DIM - 1);
        float v = W[(133 + d) * DIM + k];
        if (d != 5) v += W[132 * DIM + k];
        sSym[idx] = v;
    }
    for (int j = tid; j < L; j += blockDim.x) {
        unsigned c  = (unsigned)__ldg(seq_color  + j) & 3u;
        unsigned e  = (unsigned)__ldg(seq_entity + j) & 3u;
        unsigned s  = (unsigned)__ldg(seq_sym    + j) & 3u;
        unsigned si = (unsigned)__ldg(seq_index  + j) & 0x3FFu;
        unsigned ti = (unsigned)__ldg(token_index + j) & 0x3FFu;
        skey[j] = c | (e << 2) | (s << 4) | (si << 6) | (ti << 16);
    }
    __syncthreads();

    const int lane = tid & 31;
    const int warp = tid >> 5;
    const int half = lane >> 4;          // 0: pair A, 1: pair B
    const int k0   = (lane & 15) * 8;    // this lane's 8-float slice of the row

    // i-independent hot rows, 8 floats per lane:
    const float4 base0 = *reinterpret_cast<const float4*>(sT1  + 65 * DIM + k0);
    const float4 base1 = *reinterpret_cast<const float4*>(sT1  + 65 * DIM + k0 + 4);
    const float4 sym50 = *reinterpret_cast<const float4*>(sSym + 5 * DIM  + k0);
    const float4 sym51 = *reinterpret_cast<const float4*>(sSym + 5 * DIM  + k0 + 4);
    const float4 hot0  = make_float4(base0.x + sym50.x, base0.y + sym50.y,
                                     base0.z + sym50.z, base0.w + sym50.w);
    const float4 hot1  = make_float4(base1.x + sym51.x, base1.y + sym51.y,
                                     base1.z + sym51.z, base1.w + sym51.w);

    // Each warp owns TWO adjacent pairs per step (one STG.256 per lane).
    // p2 indexes pair-pairs; pair base p = 2*p2.
    const int halfL       = L >> 1;                          // 512
    const int np2         = (L * L) >> 1;                    // 2^19
    const int total_warps = gridDim.x * (blockDim.x >> 5);   // 9728
    const int gwarp       = blockIdx.x * (blockDim.x >> 5) + warp;

    const int step_i  = total_warps / halfL;                 // 19 for 9728/512
    const int step_j2 = total_warps - step_i * halfL;        // 0  for 9728/512

    int p2 = gwarp;
    int i  = p2 / halfL;                                     // once
    int j2 = p2 - i * halfL;

    // lane's output slice: pair base + half*128 + k0 == +lane*8
    float* __restrict__ dst = out + ((size_t)p2 * (2 * DIM)) + lane * 8;
    const size_t dst_step = (size_t)total_warps * (2 * DIM);

    while (p2 < np2) {
        const int      j  = 2 * j2 + half;
        const unsigned ki = skey[i];
        const unsigned kj = skey[j];
        const unsigned x  = ki ^ kj;

        float4 v0, v1;
        if ((x & 3u) && (x & 12u)) {
            v0 = hot0; v1 = hot1;                         // ~56%: no table reads
        } else {
            if (!(x & 3u)) {                              // same color
                const int si_i = (int)((ki >> 6) & 0x3FFu);
                const int sij  = (int)((kj >> 6) & 0x3FFu);
                int d = min(max(si_i - sij, -32), 32) + 32;
                const float* row = sT1 + d * DIM + k0;
                v0 = *reinterpret_cast<const float4*>(row);
                v1 = *reinterpret_cast<const float4*>(row + 4);
                if (si_i == sij) {                        // very rare: real token bin
                    const int ti_i = (int)((ki >> 16) & 0x3FFu);
                    const int tij  = (int)((kj >> 16) & 0x3FFu);
                    int dt = min(max(ti_i - tij, -32), 32) + 32;
                    const float* wt  = W + (66 + dt) * DIM + k0;
                    const float* w65 = W + 131 * DIM       + k0;
                    float4 a0 = __ldg(reinterpret_cast<const float4*>(wt));
                    float4 a1 = __ldg(reinterpret_cast<const float4*>(wt + 4));
                    float4 b0 = __ldg(reinterpret_cast<const float4*>(w65));
                    float4 b1 = __ldg(reinterpret_cast<const float4*>(w65 + 4));
                    v0.x += a0.x - b0.x; v0.y += a0.y - b0.y;
                    v0.z += a0.z - b0.z; v0.w += a0.w - b0.w;
                    v1.x += a1.x - b1.x; v1.y += a1.y - b1.y;
                    v1.z += a1.z - b1.z; v1.w += a1.w - b1.w;
                }
            } else {
                v0 = base0; v1 = base1;
            }
            float4 s0, s1;
            if (!(x & 12u)) {                             // same entity
                const int ss_i = (int)((ki >> 4) & 3u);
                const int ssj  = (int)((kj >> 4) & 3u);
                int ds = min(max(ss_i - ssj, -2), 2) + 2;
                const float* row = sSym + ds * DIM + k0;
                s0 = *reinterpret_cast<const float4*>(row);
                s1 = *reinterpret_cast<const float4*>(row + 4);
            } else {
                s0 = sym50; s1 = sym51;
            }
            v0.x += s0.x; v0.y += s0.y; v0.z += s0.z; v0.w += s0.w;
            v1.x += s1.x; v1.y += s1.y; v1.z += s1.z; v1.w += s1.w;
        }

        stg256_cs(dst, v0, v1);                           // one STG.256 per lane

        // advance: for this geometry step_j2==0 -> loop is just i += 19
        p2  += total_warps;
        dst += dst_step;
        j2  += step_j2;
        int wrap = (j2 >= halfL);
        i   += step_i + wrap;
        j2  -= wrap ? halfL : 0;
    }
}

extern "C" void kernel_launch(void* const* d_in, const int* in_sizes, int n_in,
                              void* d_out, int out_size)
{
    const int* seq_index   = (const int*)d_in[0];
    const int* seq_color   = (const int*)d_in[1];
    const int* seq_sym     = (const int*)d_in[2];
    const int* seq_entity  = (const int*)d_in[3];
    const int* token_index = (const int*)d_in[4];
    const float* W         = (const float*)d_in[5];
    float* out             = (float*)d_out;

    const int L = in_sizes[0];   // 1024 (B=1)

    rpe_kernel<<<NCTA, 1024>>>(seq_index, seq_color, seq_sym, seq_entity,
                               token_index, W, out, L);
}

// round 8
// speedup vs baseline: 1.5183x; 1.5183x over previous
#include <cuda_runtime.h>
#include <cuda_bf16.h>
#include <cstdint>

// Problem constants (from reference):
//   R_MAX=32, S_MAX=2 -> C_R = 66, C_S = 6, DIM_PAIR = 128
//   W rows: [0,66) = W_si, [66,132) = W_ti, 132 = w_ent, [133,139) = W_sym
#define DIM   128
#define NCTA  296    // best-measured grid (R2); 152-SM GB300 holds 304, 296 still 1 wave

__global__ __launch_bounds__(1024, 2)
void rpe_kernel(const int* __restrict__ seq_index,
                const int* __restrict__ seq_color,
                const int* __restrict__ seq_sym,
                const int* __restrict__ seq_entity,
                const int* __restrict__ token_index,
                const float* __restrict__ W,
                float* __restrict__ out,
                int L)
{
    // Tables (folded):
    //   sT1[d]  = W_si[d] + W_ti[65]      (66 rows) — d_ti==65 fast path folded in
    //   sSym[d] = W_sym[d] + (d!=5)*w_ent (6 rows)  — bij_entity <=> d_sym!=5
    //   skey[j] = color | entity<<2 | sym<<4 | seq_index<<6 | token_index<<16
    __shared__ float    sT1[66 * DIM];
    __shared__ float    sSym[6 * DIM];
    __shared__ unsigned skey[1024];

    const int tid = threadIdx.x;

    // ---- vectorized table build (float4): 4x fewer prologue LDG/STS ----
    {
        const float4* W4 = reinterpret_cast<const float4*>(W);
        float4*       T4 = reinterpret_cast<float4*>(sT1);
        // sT1: 66*128 floats = 2112 float4
        for (int idx = tid; idx < 66 * (DIM / 4); idx += blockDim.x) {
            int k4 = idx & (DIM / 4 - 1);
            float4 a = __ldg(W4 + idx);                       // W_si[d]
            float4 b = __ldg(W4 + 131 * (DIM / 4) + k4);      // W_ti[65]
            T4[idx] = make_float4(a.x + b.x, a.y + b.y, a.z + b.z, a.w + b.w);
        }
        float4* S4 = reinterpret_cast<float4*>(sSym);
        for (int idx = tid; idx < 6 * (DIM / 4); idx += blockDim.x) {
            int d  = idx / (DIM / 4);
            int k4 = idx & (DIM / 4 - 1);
            float4 a = __ldg(W4 + (133 + d) * (DIM / 4) + k4);
            if (d != 5) {
                float4 e = __ldg(W4 + 132 * (DIM / 4) + k4);  // w_ent
                a = make_float4(a.x + e.x, a.y + e.y, a.z + e.z, a.w + e.w);
            }
            S4[idx] = a;
        }
    }
    for (int j = tid; j < L; j += blockDim.x) {
        unsigned c  = (unsigned)__ldg(seq_color  + j) & 3u;
        unsigned e  = (unsigned)__ldg(seq_entity + j) & 3u;
        unsigned s  = (unsigned)__ldg(seq_sym    + j) & 3u;
        unsigned si = (unsigned)__ldg(seq_index  + j) & 0x3FFu;
        unsigned ti = (unsigned)__ldg(token_index + j) & 0x3FFu;
        skey[j] = c | (e << 2) | (s << 4) | (si << 6) | (ti << 16);
    }
    __syncthreads();

    const int lane = tid & 31;
    const int warp = tid >> 5;

    // i-independent hot rows in registers:
    const float4 base = *reinterpret_cast<const float4*>(sT1  + 65 * DIM + lane * 4);
    const float4 sym5 = *reinterpret_cast<const float4*>(sSym + 5 * DIM  + lane * 4);
    const float4 hot  = make_float4(base.x + sym5.x, base.y + sym5.y,
                                    base.z + sym5.z, base.w + sym5.w);

    // One pair per warp per step, consecutive warps on consecutive pairs:
    // keeps the chip-wide instantaneous write window contiguous (proven best
    // ordering). All index math 32-bit; only the pointer bump is 64-bit.
    const int npairs      = L * L;                        // 2^20: fits int
    const int total_warps = gridDim.x * (blockDim.x >> 5);
    const int gwarp       = blockIdx.x * (blockDim.x >> 5) + warp;

    const int step_i = total_warps / L;                   // 9   (9472/1024)
    const int step_j = total_warps - step_i * L;          // 256

    int p = gwarp;
    int i = p / L;                                        // once
    int j = p - i * L;

    float4* __restrict__ dst =
        reinterpret_cast<float4*>(out) + (size_t)p * (DIM / 4) + lane;
    const int dst_step = total_warps * (DIM / 4);

    while (p < npairs) {
        const unsigned ki = skey[i];
        const unsigned kj = skey[j];
        const unsigned x  = ki ^ kj;

        float4 v;
        if ((x & 3u) && (x & 12u)) {
            v = hot;                                      // ~56%: no table reads
        } else {
            if (!(x & 3u)) {                              // same color
                const int si_i = (int)((ki >> 6) & 0x3FFu);
                const int sij  = (int)((kj >> 6) & 0x3FFu);
                int d = min(max(si_i - sij, -32), 32) + 32;
                v = *reinterpret_cast<const float4*>(sT1 + d * DIM + lane * 4);
                if (si_i == sij) {                        // very rare: real token bin
                    const int ti_i = (int)((ki >> 16) & 0x3FFu);
                    const int tij  = (int)((kj >> 16) & 0x3FFu);
                    int dt = min(max(ti_i - tij, -32), 32) + 32;
                    float4 wt  = __ldg(reinterpret_cast<const float4*>(W + (66 + dt) * DIM + lane * 4));
                    float4 w65 = __ldg(reinterpret_cast<const float4*>(W + 131 * DIM       + lane * 4));
                    v.x += wt.x - w65.x; v.y += wt.y - w65.y;
                    v.z += wt.z - w65.z; v.w += wt.w - w65.w;
                }
            } else {
                v = base;
            }
            float4 s;
            if (!(x & 12u)) {                             // same entity
                const int ss_i = (int)((ki >> 4) & 3u);
                const int ssj  = (int)((kj >> 4) & 3u);
                int ds = min(max(ss_i - ssj, -2), 2) + 2;
                s = *reinterpret_cast<const float4*>(sSym + ds * DIM + lane * 4);
            } else {
                s = sym5;
            }
            v.x += s.x; v.y += s.y; v.z += s.z; v.w += s.w;
        }

        __stcs(dst, v);      // 128-bit .cs store: proven optimal flavor & width

        // advance one grid-stride step — branch-free 32-bit index update
        p   += total_warps;
        dst += dst_step;
        j   += step_j;
        int wrap = (j >= L);
        i   += step_i + wrap;
        j   -= wrap ? L : 0;
    }
}

extern "C" void kernel_launch(void* const* d_in, const int* in_sizes, int n_in,
                              void* d_out, int out_size)
{
    const int* seq_index   = (const int*)d_in[0];
    const int* seq_color   = (const int*)d_in[1];
    const int* seq_sym     = (const int*)d_in[2];
    const int* seq_entity  = (const int*)d_in[3];
    const int* token_index = (const int*)d_in[4];
    const float* W         = (const float*)d_in[5];
    float* out             = (float*)d_out;

    const int L = in_sizes[0];   // 1024 (B=1)

    rpe_kernel<<<NCTA, 1024>>>(seq_index, seq_color, seq_sym, seq_entity,
                               token_index, W, out, L);
}